// round 15
// baseline (speedup 1.0000x reference)
#include <cuda_runtime.h>
#include <cuda_bf16.h>

// Haar DWT, single level. Input (16,64,256,256) fp32 -> output (16,256,128,128).
// FINAL (session winner): flat grid, each thread = 4 output columns of one
// output row. 4 front-batched 128-bit loads, 4 x 128-bit stores, butterfly
// subband math (16 FADD + 16 FMUL-by-0.5 per thread; regs=28).
// Measured: 74.0us kernel, 6503 GB/s (82.1% DRAM, 81.3% of 8TB/s spec)
// = practical mixed-R/W HBM ceiling; 512 MiB traffic is irreducible.
// Beaten alternatives: naive math (+0.5-1.5%), deeper MLP (-2%), .cs loads
// (-1.3%), .cs stores (-2%), persistent grid-stride (-9%), block 512 (neutral).

static constexpr int B = 16;
static constexpr int C = 64;
static constexpr int H = 256;
static constexpr int W = 256;
static constexpr int H2 = H / 2;   // 128
static constexpr int W2 = W / 2;   // 128
static constexpr int W4 = W2 / 4;  // 32 threads per output row

__global__ __launch_bounds__(256, 8)
void dwt_haar_kernel(const float* __restrict__ x, float* __restrict__ out) {
    unsigned idx = blockIdx.x * blockDim.x + threadIdx.x;
    // idx layout: [bc][h2][w4] — consecutive threads touch consecutive memory;
    // one warp covers a full output row (reads a contiguous 2KB input row-pair,
    // writes four 512B bursts, one per sub-band plane).
    unsigned w4 = idx & (W4 - 1);            // 0..31
    unsigned h2 = (idx >> 5) & (H2 - 1);     // 0..127
    unsigned bc = idx >> 12;                 // 0..B*C-1

    const float* plane = x + (size_t)bc * (H * W);
    unsigned col = w4 * 8;                   // first of 8 input columns
    const float4* r0 = reinterpret_cast<const float4*>(plane + (size_t)(2 * h2) * W + col);
    const float4* r1 = reinterpret_cast<const float4*>(plane + (size_t)(2 * h2 + 1) * W + col);

    // Front-batch 4 independent 128-bit loads (MLP=4)
    float4 t0 = r0[0];
    float4 t1 = r0[1];
    float4 b0 = r1[0];
    float4 b1 = r1[1];

    float4 cA, cH, cV, cD;
    // Butterfly per 2x2 quad {a,b / c,d}:
    //   s0=a+d, s1=a-d, s2=b+c, s3=b-c
    //   cA=(s0+s2)*.5  cD=(s0-s2)*.5  cH=-(s1+s3)*.5  cV=(s3-s1)*.5
    {
        float a = t0.x, b = t0.y, c = b0.x, d = b0.y;
        float s0 = a + d, s1 = a - d, s2 = b + c, s3 = b - c;
        cA.x = (s0 + s2) * 0.5f;  cD.x = (s0 - s2) * 0.5f;
        cH.x = -(s1 + s3) * 0.5f; cV.x = (s3 - s1) * 0.5f;
    }
    {
        float a = t0.z, b = t0.w, c = b0.z, d = b0.w;
        float s0 = a + d, s1 = a - d, s2 = b + c, s3 = b - c;
        cA.y = (s0 + s2) * 0.5f;  cD.y = (s0 - s2) * 0.5f;
        cH.y = -(s1 + s3) * 0.5f; cV.y = (s3 - s1) * 0.5f;
    }
    {
        float a = t1.x, b = t1.y, c = b1.x, d = b1.y;
        float s0 = a + d, s1 = a - d, s2 = b + c, s3 = b - c;
        cA.z = (s0 + s2) * 0.5f;  cD.z = (s0 - s2) * 0.5f;
        cH.z = -(s1 + s3) * 0.5f; cV.z = (s3 - s1) * 0.5f;
    }
    {
        float a = t1.z, b = t1.w, c = b1.z, d = b1.w;
        float s0 = a + d, s1 = a - d, s2 = b + c, s3 = b - c;
        cA.w = (s0 + s2) * 0.5f;  cD.w = (s0 - s2) * 0.5f;
        cH.w = -(s1 + s3) * 0.5f; cV.w = (s3 - s1) * 0.5f;
    }

    // Output: planes bc*4 + {0..3} of (H2, W2)
    constexpr size_t plane_f4 = (size_t)(H2 * W2) / 4;
    size_t obase = (((size_t)bc * 4) * (H2 * W2) + (size_t)h2 * W2 + col / 2) / 4;
    float4* oA = reinterpret_cast<float4*>(out) + obase;
    oA[0 * plane_f4] = cA;
    oA[1 * plane_f4] = cH;
    oA[2 * plane_f4] = cV;
    oA[3 * plane_f4] = cD;
}

extern "C" void kernel_launch(void* const* d_in, const int* in_sizes, int n_in,
                              void* d_out, int out_size) {
    const float* x = (const float*)d_in[0];
    float* out = (float*)d_out;
    int total_threads = B * C * H2 * W4;   // 16*64*128*32 = 4,194,304
    int threads = 256;
    int blocks = total_threads / threads;  // 16384
    dwt_haar_kernel<<<blocks, threads>>>(x, out);
}

// round 16
// speedup vs baseline: 1.0031x; 1.0031x over previous
#include <cuda_runtime.h>
#include <cuda_bf16.h>

// Haar DWT, single level. Input (16,64,256,256) fp32 -> output (16,256,128,128).
// FINAL (session winner, reproduced 2x at 73.9-74.0us kernel):
//   flat grid, each thread = 4 output columns of one output row;
//   4 front-batched 128-bit loads, 4 x 128-bit stores, butterfly subband math
//   (16 FADD + 16 FMUL per thread; regs=28, occ 75%).
// Measured: 6503-6520 GB/s (82% DRAM, 81.5% of 8TB/s spec) = practical
// mixed-R/W HBM ceiling; 512 MiB traffic is irreducible; all other pipes slack.
// Beaten alternatives: naive math (+0.5-1.5%), deeper MLP (-2%), .cs loads
// (-1.3%), .cs stores (-2%), persistent grid-stride (-9%), block 512 (neutral).

static constexpr int B = 16;
static constexpr int C = 64;
static constexpr int H = 256;
static constexpr int W = 256;
static constexpr int H2 = H / 2;   // 128
static constexpr int W2 = W / 2;   // 128
static constexpr int W4 = W2 / 4;  // 32 threads per output row

__global__ __launch_bounds__(256, 8)
void dwt_haar_kernel(const float* __restrict__ x, float* __restrict__ out) {
    unsigned idx = blockIdx.x * blockDim.x + threadIdx.x;
    // idx layout: [bc][h2][w4] — consecutive threads touch consecutive memory;
    // one warp covers a full output row (reads a contiguous 2KB input row-pair,
    // writes four 512B bursts, one per sub-band plane).
    unsigned w4 = idx & (W4 - 1);            // 0..31
    unsigned h2 = (idx >> 5) & (H2 - 1);     // 0..127
    unsigned bc = idx >> 12;                 // 0..B*C-1

    const float* plane = x + (size_t)bc * (H * W);
    unsigned col = w4 * 8;                   // first of 8 input columns
    const float4* r0 = reinterpret_cast<const float4*>(plane + (size_t)(2 * h2) * W + col);
    const float4* r1 = reinterpret_cast<const float4*>(plane + (size_t)(2 * h2 + 1) * W + col);

    // Front-batch 4 independent 128-bit loads (MLP=4)
    float4 t0 = r0[0];
    float4 t1 = r0[1];
    float4 b0 = r1[0];
    float4 b1 = r1[1];

    float4 cA, cH, cV, cD;
    // Butterfly per 2x2 quad {a,b / c,d}:
    //   s0=a+d, s1=a-d, s2=b+c, s3=b-c
    //   cA=(s0+s2)*.5  cD=(s0-s2)*.5  cH=-(s1+s3)*.5  cV=(s3-s1)*.5
    {
        float a = t0.x, b = t0.y, c = b0.x, d = b0.y;
        float s0 = a + d, s1 = a - d, s2 = b + c, s3 = b - c;
        cA.x = (s0 + s2) * 0.5f;  cD.x = (s0 - s2) * 0.5f;
        cH.x = -(s1 + s3) * 0.5f; cV.x = (s3 - s1) * 0.5f;
    }
    {
        float a = t0.z, b = t0.w, c = b0.z, d = b0.w;
        float s0 = a + d, s1 = a - d, s2 = b + c, s3 = b - c;
        cA.y = (s0 + s2) * 0.5f;  cD.y = (s0 - s2) * 0.5f;
        cH.y = -(s1 + s3) * 0.5f; cV.y = (s3 - s1) * 0.5f;
    }
    {
        float a = t1.x, b = t1.y, c = b1.x, d = b1.y;
        float s0 = a + d, s1 = a - d, s2 = b + c, s3 = b - c;
        cA.z = (s0 + s2) * 0.5f;  cD.z = (s0 - s2) * 0.5f;
        cH.z = -(s1 + s3) * 0.5f; cV.z = (s3 - s1) * 0.5f;
    }
    {
        float a = t1.z, b = t1.w, c = b1.z, d = b1.w;
        float s0 = a + d, s1 = a - d, s2 = b + c, s3 = b - c;
        cA.w = (s0 + s2) * 0.5f;  cD.w = (s0 - s2) * 0.5f;
        cH.w = -(s1 + s3) * 0.5f; cV.w = (s3 - s1) * 0.5f;
    }

    // Output: planes bc*4 + {0..3} of (H2, W2)
    constexpr size_t plane_f4 = (size_t)(H2 * W2) / 4;
    size_t obase = (((size_t)bc * 4) * (H2 * W2) + (size_t)h2 * W2 + col / 2) / 4;
    float4* oA = reinterpret_cast<float4*>(out) + obase;
    oA[0 * plane_f4] = cA;
    oA[1 * plane_f4] = cH;
    oA[2 * plane_f4] = cV;
    oA[3 * plane_f4] = cD;
}

extern "C" void kernel_launch(void* const* d_in, const int* in_sizes, int n_in,
                              void* d_out, int out_size) {
    const float* x = (const float*)d_in[0];
    float* out = (float*)d_out;
    int total_threads = B * C * H2 * W4;   // 16*64*128*32 = 4,194,304
    int threads = 256;
    int blocks = total_threads / threads;  // 16384
    dwt_haar_kernel<<<blocks, threads>>>(x, out);
}